// round 9
// baseline (speedup 1.0000x reference)
#include <cuda_runtime.h>
#include <cuda_bf16.h>
#include <cstdint>

#define B_  32
#define S_  512
#define D_  512
#define H_  8
#define DK_ 64
#define NEG_INF_ (-1e30f)

// ---------------------------------------------------------------------------
// Packed bf16-pair (u32 = 2 bf16 along K) scratch, hi/lo split arrays.
// ---------------------------------------------------------------------------
#define WQKV_WORDS (3*8*256*64)          // [mat][h][kpair 0..255][n 0..63]
#define WO_WORDS   (256*512)             // [kpair 0..255][n 0..511]
#define QKV_WORDS  (B_*H_*S_*(DK_/2))    // [bh][s][dkpair 0..31]
#define HH_WORDS   (B_*S_*H_*(DK_/2))    // [b*S+s][256 words]

__device__ uint32_t g_Wqkv_hi[WQKV_WORDS], g_Wqkv_lo[WQKV_WORDS];
__device__ uint32_t g_Wo_hi[WO_WORDS],     g_Wo_lo[WO_WORDS];
__device__ uint32_t g_Qhi[QKV_WORDS], g_Qlo[QKV_WORDS];
__device__ uint32_t g_Khi[QKV_WORDS], g_Klo[QKV_WORDS];
__device__ uint32_t g_Vhi[QKV_WORDS], g_Vlo[QKV_WORDS];
__device__ uint32_t g_Hhi[HH_WORDS],  g_Hlo[HH_WORDS];

__device__ __forceinline__ uint32_t pack_bf2(float x0, float x1) {
    unsigned short u0 = __bfloat16_as_ushort(__float2bfloat16_rn(x0));
    unsigned short u1 = __bfloat16_as_ushort(__float2bfloat16_rn(x1));
    return ((uint32_t)u1 << 16) | (uint32_t)u0;
}
// x = hi + lo with hi,lo bf16; word packs (k even -> low half, k odd -> high half)
__device__ __forceinline__ void split2(float x0, float x1, uint32_t& hi, uint32_t& lo) {
    __nv_bfloat16 h0 = __float2bfloat16_rn(x0);
    __nv_bfloat16 h1 = __float2bfloat16_rn(x1);
    hi = ((uint32_t)__bfloat16_as_ushort(h1) << 16) | (uint32_t)__bfloat16_as_ushort(h0);
    lo = pack_bf2(x0 - __bfloat162float(h0), x1 - __bfloat162float(h1));
}

// D += A(16x16 row) * B(16x8 col), bf16 in, fp32 accum.
__device__ __forceinline__ void mma16(float* c,
    uint32_t a0, uint32_t a1, uint32_t a2, uint32_t a3,
    uint32_t b0, uint32_t b1)
{
    asm volatile(
        "mma.sync.aligned.m16n8k16.row.col.f32.bf16.bf16.f32 "
        "{%0,%1,%2,%3},{%4,%5,%6,%7},{%8,%9},{%0,%1,%2,%3};"
        : "+f"(c[0]), "+f"(c[1]), "+f"(c[2]), "+f"(c[3])
        : "r"(a0), "r"(a1), "r"(a2), "r"(a3), "r"(b0), "r"(b1));
}

// ---------------------------------------------------------------------------
// Kernel 0: weight prep — split to bf16 hi/lo and transpose to [kpair][n] words.
// One word = (W[2j][n], W[2j+1][n]).  Run once per launch (~0.5M words).
// ---------------------------------------------------------------------------
__global__ __launch_bounds__(256) void prep_w(
    const float* __restrict__ Wq, const float* __restrict__ Wk,
    const float* __restrict__ Wv, const float* __restrict__ Wo)
{
    int idx = blockIdx.x * 256 + threadIdx.x;
    if (idx < WQKV_WORDS) {
        int mat = idx / (8 * 256 * 64);
        int rem = idx % (8 * 256 * 64);
        int h = rem >> 14;            // 256*64 = 16384
        int w = rem & 16383;
        int j = w >> 6, n = w & 63;
        const float* W = ((mat == 0) ? Wq : (mat == 1 ? Wk : Wv))
                       + ((size_t)h * D_ + 2 * j) * DK_ + n;
        uint32_t hi, lo; split2(W[0], W[DK_], hi, lo);
        g_Wqkv_hi[idx] = hi; g_Wqkv_lo[idx] = lo;
    } else {
        int w = idx - WQKV_WORDS;
        if (w < WO_WORDS) {
            int j = w >> 9, n = w & 511;
            const float* W = Wo + (size_t)(2 * j) * D_ + n;
            uint32_t hi, lo; split2(W[0], W[D_], hi, lo);
            g_Wo_hi[w] = hi; g_Wo_lo[w] = lo;
        }
    }
}

// ---------------------------------------------------------------------------
// Kernel 1: QKV projections, bf16x2 MMA.
// C[128 x 128] = X[128 x 512] @ W[512 x 128] (+bias); 128 cols = 2 heads x 64.
// grid (4 s-tiles, B=32, 12 = 3 mats x 4 head-pairs), block 256.
// ---------------------------------------------------------------------------
__global__ __launch_bounds__(256) void qkv_mma(
    const float* __restrict__ x, const float* __restrict__ bias)
{
    __shared__ uint32_t Xhi[128 * 20], Xlo[128 * 20];   // [row][kpair 0..15], pad 4
    __shared__ uint32_t Whi[128 * 20], Wlo[128 * 20];   // [col][kpair 0..15]

    const int t    = threadIdx.x;
    const int warp = t >> 5, lane = t & 31;
    const int gid  = lane >> 2, tig = lane & 3;
    const int wrow = warp * 16;

    const int s0  = blockIdx.x * 128;
    const int b   = blockIdx.y;
    const int g   = blockIdx.z;
    const int mat = g >> 2;
    const int hp  = g & 3;

    const float* A = x + ((size_t)b * S_ + s0) * D_;
    uint32_t* Ohi = (mat == 0) ? g_Qhi : (mat == 1 ? g_Khi : g_Vhi);
    uint32_t* Olo = (mat == 0) ? g_Qlo : (mat == 1 ? g_Klo : g_Vlo);

    float acc[16][4];
    #pragma unroll
    for (int nt = 0; nt < 16; nt++) { acc[nt][0]=0.f; acc[nt][1]=0.f; acc[nt][2]=0.f; acc[nt][3]=0.f; }

    for (int d0 = 0; d0 < D_; d0 += 32) {
        // X tile 128x32 floats -> 128x16 words: 4 float4 per thread
        #pragma unroll
        for (int i = 0; i < 4; i++) {
            int v = t + 256 * i;
            int r = v >> 3, c4 = v & 7;
            float4 xv = *(const float4*)&A[(size_t)r * D_ + d0 + c4 * 4];
            uint32_t h0, l0, h1, l1;
            split2(xv.x, xv.y, h0, l0);
            split2(xv.z, xv.w, h1, l1);
            Xhi[r * 20 + 2 * c4]     = h0;  Xhi[r * 20 + 2 * c4 + 1] = h1;
            Xlo[r * 20 + 2 * c4]     = l0;  Xlo[r * 20 + 2 * c4 + 1] = l1;
        }
        // W tile: prepped words, direct copy (coalesced over col)
        #pragma unroll
        for (int i = 0; i < 8; i++) {
            int v = t + 256 * i;
            int col = v & 127, j = v >> 7;           // j 0..15
            int hloc = col >> 6, nn = col & 63;
            size_t gi = ((size_t)(mat * H_ + 2 * hp + hloc) * 256 + (d0 >> 1) + j) * 64 + nn;
            Whi[col * 20 + j] = g_Wqkv_hi[gi];
            Wlo[col * 20 + j] = g_Wqkv_lo[gi];
        }
        __syncthreads();

        #pragma unroll
        for (int ch = 0; ch < 2; ch++) {
            uint32_t ah0 = Xhi[(wrow + gid)     * 20 + ch * 8 + tig];
            uint32_t ah1 = Xhi[(wrow + gid + 8) * 20 + ch * 8 + tig];
            uint32_t ah2 = Xhi[(wrow + gid)     * 20 + ch * 8 + tig + 4];
            uint32_t ah3 = Xhi[(wrow + gid + 8) * 20 + ch * 8 + tig + 4];
            uint32_t al0 = Xlo[(wrow + gid)     * 20 + ch * 8 + tig];
            uint32_t al1 = Xlo[(wrow + gid + 8) * 20 + ch * 8 + tig];
            uint32_t al2 = Xlo[(wrow + gid)     * 20 + ch * 8 + tig + 4];
            uint32_t al3 = Xlo[(wrow + gid + 8) * 20 + ch * 8 + tig + 4];
            #pragma unroll
            for (int nt = 0; nt < 16; nt++) {
                uint32_t bh0 = Whi[(nt * 8 + gid) * 20 + ch * 8 + tig];
                uint32_t bh1 = Whi[(nt * 8 + gid) * 20 + ch * 8 + tig + 4];
                uint32_t bl0 = Wlo[(nt * 8 + gid) * 20 + ch * 8 + tig];
                uint32_t bl1 = Wlo[(nt * 8 + gid) * 20 + ch * 8 + tig + 4];
                mma16(acc[nt], ah0, ah1, ah2, ah3, bh0, bh1);
                mma16(acc[nt], ah0, ah1, ah2, ah3, bl0, bl1);
                mma16(acc[nt], al0, al1, al2, al3, bh0, bh1);
            }
        }
        __syncthreads();
    }

    const float bs = bias[0];
    const int row0 = s0 + wrow + gid;
    #pragma unroll
    for (int nt = 0; nt < 16; nt++) {
        int col = nt * 8 + 2 * tig;                  // even; pair within one head
        int hh  = col >> 6;
        int dkp = (col & 63) >> 1;
        size_t base = ((size_t)(b * H_ + 2 * hp + hh) * S_);
        uint32_t hi0, lo0, hi1, lo1;
        split2(acc[nt][0] + bs, acc[nt][1] + bs, hi0, lo0);
        split2(acc[nt][2] + bs, acc[nt][3] + bs, hi1, lo1);
        Ohi[(base + row0)     * 32 + dkp] = hi0;  Olo[(base + row0)     * 32 + dkp] = lo0;
        Ohi[(base + row0 + 8) * 32 + dkp] = hi1;  Olo[(base + row0 + 8) * 32 + dkp] = lo1;
    }
}

// ---------------------------------------------------------------------------
// Kernel 2: fused attention, bf16x2 MMA + fp32 online softmax.
// grid (4 q-tiles of 128, 256 bh), block 256 = 8 warps x 16 q-rows.
// Dyn smem words: Khi/Klo [64*36], Vthi/Vtlo [64*36] (dk x keypair),
//                 Phi/Plo [128*36], mks[64]
// ---------------------------------------------------------------------------
#define KS_OFF   0
#define KL_OFF   (64*36)
#define VH_OFF   (2*64*36)
#define VL_OFF   (3*64*36)
#define PH_OFF   (4*64*36)
#define PL_OFF   (4*64*36 + 128*36)
#define MK_OFF   (4*64*36 + 2*128*36)
#define ATTN_SMEM_WORDS (MK_OFF + 64)

__global__ __launch_bounds__(256) void attn_mma(const int* __restrict__ mask)
{
    extern __shared__ uint32_t sm[];
    uint32_t* Khi_s = sm + KS_OFF;
    uint32_t* Klo_s = sm + KL_OFF;
    uint32_t* Vthi  = sm + VH_OFF;
    uint32_t* Vtlo  = sm + VL_OFF;
    uint32_t* Phi_s = sm + PH_OFF;
    uint32_t* Plo_s = sm + PL_OFF;
    float*    mks   = (float*)(sm + MK_OFF);
    unsigned short* Vthi_u = (unsigned short*)Vthi;
    unsigned short* Vtlo_u = (unsigned short*)Vtlo;

    const int t    = threadIdx.x;
    const int warp = t >> 5, lane = t & 31;
    const int gid  = lane >> 2, tig = lane & 3;
    const int wrow = warp * 16;

    const int q0 = blockIdx.x * 128;
    const int bh = blockIdx.y;
    const int b  = bh >> 3, h = bh & 7;

    // Stage Q words (128 x 32) into P region, distribute fragments.
    #pragma unroll
    for (int i = 0; i < 4; i++) {
        int v = t + 256 * i;
        int r = v >> 3, j4 = (v & 7) * 4;
        *(uint4*)&Phi_s[r * 36 + j4] = *(const uint4*)&g_Qhi[((size_t)bh * S_ + q0 + r) * 32 + j4];
        *(uint4*)&Plo_s[r * 36 + j4] = *(const uint4*)&g_Qlo[((size_t)bh * S_ + q0 + r) * 32 + j4];
    }
    __syncthreads();

    uint32_t qh[4][4], ql[4][4];
    #pragma unroll
    for (int c = 0; c < 4; c++) {
        qh[c][0] = Phi_s[(wrow + gid)     * 36 + c * 8 + tig];
        qh[c][1] = Phi_s[(wrow + gid + 8) * 36 + c * 8 + tig];
        qh[c][2] = Phi_s[(wrow + gid)     * 36 + c * 8 + tig + 4];
        qh[c][3] = Phi_s[(wrow + gid + 8) * 36 + c * 8 + tig + 4];
        ql[c][0] = Plo_s[(wrow + gid)     * 36 + c * 8 + tig];
        ql[c][1] = Plo_s[(wrow + gid + 8) * 36 + c * 8 + tig];
        ql[c][2] = Plo_s[(wrow + gid)     * 36 + c * 8 + tig + 4];
        ql[c][3] = Plo_s[(wrow + gid + 8) * 36 + c * 8 + tig + 4];
    }
    __syncthreads();

    float o[8][4];
    #pragma unroll
    for (int nt = 0; nt < 8; nt++) { o[nt][0]=0.f; o[nt][1]=0.f; o[nt][2]=0.f; o[nt][3]=0.f; }
    float m0 = __int_as_float(0xff800000), m1 = m0;
    float l0 = 0.f, l1 = 0.f;

    for (int t0 = 0; t0 < S_; t0 += 64) {
        // K tile: direct word copy [key][dkpair]
        #pragma unroll
        for (int i = 0; i < 2; i++) {
            int v = t + 256 * i;
            int r = v >> 3, j4 = (v & 7) * 4;
            *(uint4*)&Khi_s[r * 36 + j4] = *(const uint4*)&g_Khi[((size_t)bh * S_ + t0 + r) * 32 + j4];
            *(uint4*)&Klo_s[r * 36 + j4] = *(const uint4*)&g_Klo[((size_t)bh * S_ + t0 + r) * 32 + j4];
        }
        // V tile: transpose to [dk][keypair] via u16 stores (lane-staggered)
        #pragma unroll
        for (int arr = 0; arr < 2; arr++) {
            const uint32_t* src = arr ? g_Vlo : g_Vhi;
            unsigned short* dst = arr ? Vtlo_u : Vthi_u;
            #pragma unroll
            for (int i = 0; i < 2; i++) {
                int v = t + 256 * i;
                int key = v >> 3, j4 = (v & 7) * 4;
                uint4 wv = *(const uint4*)&src[((size_t)bh * S_ + t0 + key) * 32 + j4];
                uint32_t ws[4] = {wv.x, wv.y, wv.z, wv.w};
                int kp = key >> 1, half = key & 1;
                #pragma unroll
                for (int mm = 0; mm < 4; mm++) {
                    int m = (mm + t) & 3;
                    int dk0 = 2 * (j4 + m);
                    uint32_t w = ws[m];
                    dst[(dk0 * 36 + kp) * 2 + half]       = (unsigned short)(w & 0xffff);
                    dst[((dk0 + 1) * 36 + kp) * 2 + half] = (unsigned short)(w >> 16);
                }
            }
        }
        if (t < 64) mks[t] = (float)mask[b * S_ + t0 + t];
        __syncthreads();

        // Scores: S[128 x 64] = Q @ K^T (3-term)
        float s[8][4];
        #pragma unroll
        for (int nt = 0; nt < 8; nt++) { s[nt][0]=0.f; s[nt][1]=0.f; s[nt][2]=0.f; s[nt][3]=0.f; }
        #pragma unroll
        for (int ch = 0; ch < 4; ch++) {
            #pragma unroll
            for (int nt = 0; nt < 8; nt++) {
                uint32_t bh0 = Khi_s[(nt * 8 + gid) * 36 + ch * 8 + tig];
                uint32_t bh1 = Khi_s[(nt * 8 + gid) * 36 + ch * 8 + tig + 4];
                uint32_t bl0 = Klo_s[(nt * 8 + gid) * 36 + ch * 8 + tig];
                uint32_t bl1 = Klo_s[(nt * 8 + gid) * 36 + ch * 8 + tig + 4];
                mma16(s[nt], qh[ch][0], qh[ch][1], qh[ch][2], qh[ch][3], bh0, bh1);
                mma16(s[nt], qh[ch][0], qh[ch][1], qh[ch][2], qh[ch][3], bl0, bl1);
                mma16(s[nt], ql[ch][0], ql[ch][1], ql[ch][2], ql[ch][3], bh0, bh1);
            }
        }

        // Scale + mask
        #pragma unroll
        for (int nt = 0; nt < 8; nt++) {
            int col = nt * 8 + 2 * tig;
            float mk0 = mks[col], mk1 = mks[col + 1];
            s[nt][0] = (mk0 != 0.f) ? s[nt][0] * 0.125f : NEG_INF_;
            s[nt][1] = (mk1 != 0.f) ? s[nt][1] * 0.125f : NEG_INF_;
            s[nt][2] = (mk0 != 0.f) ? s[nt][2] * 0.125f : NEG_INF_;
            s[nt][3] = (mk1 != 0.f) ? s[nt][3] * 0.125f : NEG_INF_;
        }

        // Row maxes (quad reduction)
        float ml0 = fmaxf(s[0][0], s[0][1]), ml1 = fmaxf(s[0][2], s[0][3]);
        #pragma unroll
        for (int nt = 1; nt < 8; nt++) {
            ml0 = fmaxf(ml0, fmaxf(s[nt][0], s[nt][1]));
            ml1 = fmaxf(ml1, fmaxf(s[nt][2], s[nt][3]));
        }
        ml0 = fmaxf(ml0, __shfl_xor_sync(0xffffffffu, ml0, 1));
        ml0 = fmaxf(ml0, __shfl_xor_sync(0xffffffffu, ml0, 2));
        ml1 = fmaxf(ml1, __shfl_xor_sync(0xffffffffu, ml1, 1));
        ml1 = fmaxf(ml1, __shfl_xor_sync(0xffffffffu, ml1, 2));

        float mn0 = fmaxf(m0, ml0), mn1 = fmaxf(m1, ml1);
        float c0 = __expf(m0 - mn0), c1 = __expf(m1 - mn1);
        m0 = mn0; m1 = mn1;
        #pragma unroll
        for (int nt = 0; nt < 8; nt++) {
            o[nt][0] *= c0; o[nt][1] *= c0;
            o[nt][2] *= c1; o[nt][3] *= c1;
        }

        // Exponentiate, row-sum, write split P words [q][keypair]
        float ps0 = 0.f, ps1 = 0.f;
        const int pr0 = (wrow + gid) * 36, pr1 = (wrow + gid + 8) * 36;
        #pragma unroll
        for (int nt = 0; nt < 8; nt++) {
            int kp = nt * 4 + tig;
            float p00 = __expf(s[nt][0] - m0);
            float p01 = __expf(s[nt][1] - m0);
            float p10 = __expf(s[nt][2] - m1);
            float p11 = __expf(s[nt][3] - m1);
            ps0 += p00 + p01; ps1 += p10 + p11;
            uint32_t hi, lo;
            split2(p00, p01, hi, lo);
            Phi_s[pr0 + kp] = hi; Plo_s[pr0 + kp] = lo;
            split2(p10, p11, hi, lo);
            Phi_s[pr1 + kp] = hi; Plo_s[pr1 + kp] = lo;
        }
        ps0 += __shfl_xor_sync(0xffffffffu, ps0, 1);
        ps0 += __shfl_xor_sync(0xffffffffu, ps0, 2);
        ps1 += __shfl_xor_sync(0xffffffffu, ps1, 1);
        ps1 += __shfl_xor_sync(0xffffffffu, ps1, 2);
        l0 = l0 * c0 + ps0;
        l1 = l1 * c1 + ps1;

        __syncwarp();

        // PV: O += P @ V (3-term), B from transposed V [dk][keypair]
        #pragma unroll
        for (int ch = 0; ch < 4; ch++) {
            uint32_t ah0 = Phi_s[(wrow + gid)     * 36 + ch * 8 + tig];
            uint32_t ah1 = Phi_s[(wrow + gid + 8) * 36 + ch * 8 + tig];
            uint32_t ah2 = Phi_s[(wrow + gid)     * 36 + ch * 8 + tig + 4];
            uint32_t ah3 = Phi_s[(wrow + gid + 8) * 36 + ch * 8 + tig + 4];
            uint32_t al0 = Plo_s[(wrow + gid)     * 36 + ch * 8 + tig];
            uint32_t al1 = Plo_s[(wrow + gid + 8) * 36 + ch * 8 + tig];
            uint32_t al2 = Plo_s[(wrow + gid)     * 36 + ch * 8 + tig + 4];
            uint32_t al3 = Plo_s[(wrow + gid + 8) * 36 + ch * 8 + tig + 4];
            #pragma unroll
            for (int nt = 0; nt < 8; nt++) {
                uint32_t bh0 = Vthi[(nt * 8 + gid) * 36 + ch * 8 + tig];
                uint32_t bh1 = Vthi[(nt * 8 + gid) * 36 + ch * 8 + tig + 4];
                uint32_t bl0 = Vtlo[(nt * 8 + gid) * 36 + ch * 8 + tig];
                uint32_t bl1 = Vtlo[(nt * 8 + gid) * 36 + ch * 8 + tig + 4];
                mma16(o[nt], ah0, ah1, ah2, ah3, bh0, bh1);
                mma16(o[nt], ah0, ah1, ah2, ah3, bl0, bl1);
                mma16(o[nt], al0, al1, al2, al3, bh0, bh1);
            }
        }
        __syncthreads();
    }

    const float inv0 = 1.f / l0, inv1 = 1.f / l1;
    const int q = q0 + wrow + gid;
    #pragma unroll
    for (int nt = 0; nt < 8; nt++) {
        int kp = nt * 4 + tig;                      // dk-pair within head
        uint32_t hi, lo;
        split2(o[nt][0] * inv0, o[nt][1] * inv0, hi, lo);
        g_Hhi[((size_t)(b * S_ + q)) * 256 + h * 32 + kp] = hi;
        g_Hlo[((size_t)(b * S_ + q)) * 256 + h * 32 + kp] = lo;
        split2(o[nt][2] * inv1, o[nt][3] * inv1, hi, lo);
        g_Hhi[((size_t)(b * S_ + q + 8)) * 256 + h * 32 + kp] = hi;
        g_Hlo[((size_t)(b * S_ + q + 8)) * 256 + h * 32 + kp] = lo;
    }
}

// ---------------------------------------------------------------------------
// Kernel 3: output projection, bf16x2 MMA.
// out[16384 x 512] = heads @ Wo + bias.  grid (128, 4), block 256.
// ---------------------------------------------------------------------------
__global__ __launch_bounds__(256) void out_mma(
    const float* __restrict__ bias, float* __restrict__ out)
{
    __shared__ uint32_t Ahi[128 * 20], Alo[128 * 20];
    __shared__ uint32_t Bhi[128 * 20], Blo[128 * 20];

    const int t    = threadIdx.x;
    const int warp = t >> 5, lane = t & 31;
    const int gid  = lane >> 2, tig = lane & 3;
    const int wrow = warp * 16;

    const int m0 = blockIdx.x * 128;
    const int n0 = blockIdx.y * 128;

    float acc[16][4];
    #pragma unroll
    for (int nt = 0; nt < 16; nt++) { acc[nt][0]=0.f; acc[nt][1]=0.f; acc[nt][2]=0.f; acc[nt][3]=0.f; }

    for (int d0 = 0; d0 < D_; d0 += 32) {
        // A tile: copy packed head words [row][kpair]
        #pragma unroll
        for (int i = 0; i < 2; i++) {
            int v = t + 256 * i;
            int r = v >> 2, j4 = (v & 3) * 4;
            *(uint4*)&Ahi[r * 20 + j4] = *(const uint4*)&g_Hhi[(size_t)(m0 + r) * 256 + (d0 >> 1) + j4];
            *(uint4*)&Alo[r * 20 + j4] = *(const uint4*)&g_Hlo[(size_t)(m0 + r) * 256 + (d0 >> 1) + j4];
        }
        // B tile: prepped Wo words [col][kpair] (coalesced over col)
        #pragma unroll
        for (int i = 0; i < 8; i++) {
            int v = t + 256 * i;
            int col = v & 127, j = v >> 7;
            size_t gi = (size_t)((d0 >> 1) + j) * 512 + n0 + col;
            Bhi[col * 20 + j] = g_Wo_hi[gi];
            Blo[col * 20 + j] = g_Wo_lo[gi];
        }
        __syncthreads();

        #pragma unroll
        for (int ch = 0; ch < 2; ch++) {
            uint32_t ah0 = Ahi[(wrow + gid)     * 20 + ch * 8 + tig];
            uint32_t ah1 = Ahi[(wrow + gid + 8) * 20 + ch * 8 + tig];
            uint32_t ah2 = Ahi[(wrow + gid)     * 20 + ch * 8 + tig + 4];
            uint32_t ah3 = Ahi[(wrow + gid + 8) * 20 + ch * 8 + tig + 4];
            uint32_t al0 = Alo[(wrow + gid)     * 20 + ch * 8 + tig];
            uint32_t al1 = Alo[(wrow + gid + 8) * 20 + ch * 8 + tig];
            uint32_t al2 = Alo[(wrow + gid)     * 20 + ch * 8 + tig + 4];
            uint32_t al3 = Alo[(wrow + gid + 8) * 20 + ch * 8 + tig + 4];
            #pragma unroll
            for (int nt = 0; nt < 16; nt++) {
                uint32_t bh0 = Bhi[(nt * 8 + gid) * 20 + ch * 8 + tig];
                uint32_t bh1 = Bhi[(nt * 8 + gid) * 20 + ch * 8 + tig + 4];
                uint32_t bl0 = Blo[(nt * 8 + gid) * 20 + ch * 8 + tig];
                uint32_t bl1 = Blo[(nt * 8 + gid) * 20 + ch * 8 + tig + 4];
                mma16(acc[nt], ah0, ah1, ah2, ah3, bh0, bh1);
                mma16(acc[nt], ah0, ah1, ah2, ah3, bl0, bl1);
                mma16(acc[nt], al0, al1, al2, al3, bh0, bh1);
            }
        }
        __syncthreads();
    }

    const float bs = bias[0];
    const int row0 = m0 + wrow + gid;
    #pragma unroll
    for (int nt = 0; nt < 16; nt++) {
        int col = n0 + nt * 8 + 2 * tig;
        *(float2*)&out[(size_t)row0 * D_ + col]       = make_float2(acc[nt][0] + bs, acc[nt][1] + bs);
        *(float2*)&out[(size_t)(row0 + 8) * D_ + col] = make_float2(acc[nt][2] + bs, acc[nt][3] + bs);
    }
}

// ---------------------------------------------------------------------------
extern "C" void kernel_launch(void* const* d_in, const int* in_sizes, int n_in,
                              void* d_out, int out_size)
{
    const float* x    = (const float*)d_in[0];
    const int*   mask = (const int*)  d_in[1];
    const float* Wq   = (const float*)d_in[2];
    const float* Wk   = (const float*)d_in[3];
    const float* Wv   = (const float*)d_in[4];
    const float* Wo   = (const float*)d_in[5];
    const float* bias = (const float*)d_in[6];
    float*       out  = (float*)d_out;

    static bool attr_set = false;
    if (!attr_set) {
        cudaFuncSetAttribute(attn_mma, cudaFuncAttributeMaxDynamicSharedMemorySize,
                             ATTN_SMEM_WORDS * (int)sizeof(uint32_t));
        attr_set = true;
    }

    prep_w<<<(WQKV_WORDS + WO_WORDS) / 256, 256>>>(Wq, Wk, Wv, Wo);
    qkv_mma<<<dim3(4, 32, 12), 256>>>(x, bias);
    attn_mma<<<dim3(4, 256), 256, ATTN_SMEM_WORDS * sizeof(uint32_t)>>>(mask);
    out_mma<<<dim3(128, 4), 256>>>(bias, out);
}

// round 10
// speedup vs baseline: 1.2207x; 1.2207x over previous
#include <cuda_runtime.h>
#include <cuda_bf16.h>
#include <cstdint>

#define B_  32
#define S_  512
#define D_  512
#define H_  8
#define DK_ 64
#define NEG_INF_ (-1e30f)

// ---------------------------------------------------------------------------
// Packed bf16-pair (u32 = 2 bf16 along K; even k in low 16) hi/lo split arrays.
// ---------------------------------------------------------------------------
#define WQKV_WORDS (3*8*64*256)          // [(mat*8+h)*64+n][kpair 0..255]
#define WO_WORDS   (512*256)             // [n 0..511][kpair 0..255]
#define X_WORDS    (B_*S_*256)           // [b*S+s][dpair 0..255]
#define QKV_WORDS  (B_*H_*S_*32)         // [bh][s][dkpair 0..31]
#define VT_WORDS   (B_*H_*DK_*256)       // [bh][dk][spair 0..255]
#define HH_WORDS   (B_*S_*H_*32)         // [b*S+s][256 words]

__device__ uint32_t g_Wqkv_hi[WQKV_WORDS], g_Wqkv_lo[WQKV_WORDS];
__device__ uint32_t g_Wo_hi[WO_WORDS],     g_Wo_lo[WO_WORDS];
__device__ uint32_t g_Xhi[X_WORDS],   g_Xlo[X_WORDS];
__device__ uint32_t g_Qhi[QKV_WORDS], g_Qlo[QKV_WORDS];
__device__ uint32_t g_Khi[QKV_WORDS], g_Klo[QKV_WORDS];
__device__ uint32_t g_Vhi[QKV_WORDS], g_Vlo[QKV_WORDS];
__device__ uint32_t g_Vthi[VT_WORDS], g_Vtlo[VT_WORDS];
__device__ uint32_t g_Hhi[HH_WORDS],  g_Hlo[HH_WORDS];

__device__ __forceinline__ uint32_t pack_bf2(float x0, float x1) {
    unsigned short u0 = __bfloat16_as_ushort(__float2bfloat16_rn(x0));
    unsigned short u1 = __bfloat16_as_ushort(__float2bfloat16_rn(x1));
    return ((uint32_t)u1 << 16) | (uint32_t)u0;
}
__device__ __forceinline__ void split2(float x0, float x1, uint32_t& hi, uint32_t& lo) {
    __nv_bfloat16 h0 = __float2bfloat16_rn(x0);
    __nv_bfloat16 h1 = __float2bfloat16_rn(x1);
    hi = ((uint32_t)__bfloat16_as_ushort(h1) << 16) | (uint32_t)__bfloat16_as_ushort(h0);
    lo = pack_bf2(x0 - __bfloat162float(h0), x1 - __bfloat162float(h1));
}

__device__ __forceinline__ void mma16(float* c,
    uint32_t a0, uint32_t a1, uint32_t a2, uint32_t a3,
    uint32_t b0, uint32_t b1)
{
    asm volatile(
        "mma.sync.aligned.m16n8k16.row.col.f32.bf16.bf16.f32 "
        "{%0,%1,%2,%3},{%4,%5,%6,%7},{%8,%9},{%0,%1,%2,%3};"
        : "+f"(c[0]), "+f"(c[1]), "+f"(c[2]), "+f"(c[3])
        : "r"(a0), "r"(a1), "r"(a2), "r"(a3), "r"(b0), "r"(b1));
}

__device__ __forceinline__ void cp16(uint32_t dst_smem, const void* src) {
    asm volatile("cp.async.cg.shared.global [%0], [%1], 16;"
                 :: "r"(dst_smem), "l"(src));
}
#define CP_COMMIT() asm volatile("cp.async.commit_group;")
#define CP_WAIT1()  asm volatile("cp.async.wait_group 1;")
#define CP_WAIT0()  asm volatile("cp.async.wait_group 0;")

// ---------------------------------------------------------------------------
// Kernel 0a: weight prep -> [row=n-ish][kpair] packed words (cp.async friendly).
// ---------------------------------------------------------------------------
__global__ __launch_bounds__(256) void prep_w(
    const float* __restrict__ Wq, const float* __restrict__ Wk,
    const float* __restrict__ Wv, const float* __restrict__ Wo)
{
    int idx = blockIdx.x * 256 + threadIdx.x;
    if (idx < WQKV_WORDS) {
        int kp = idx & 255;
        int r  = idx >> 8;
        int n  = r & 63;
        int h  = (r >> 6) & 7;
        int mat = r >> 9;
        const float* W = ((mat == 0) ? Wq : (mat == 1 ? Wk : Wv))
                       + ((size_t)h * D_ + 2 * kp) * DK_ + n;
        uint32_t hi, lo; split2(W[0], W[DK_], hi, lo);
        g_Wqkv_hi[idx] = hi; g_Wqkv_lo[idx] = lo;
    } else {
        int w = idx - WQKV_WORDS;
        if (w < WO_WORDS) {
            int kp = w & 255;
            int n  = w >> 8;
            const float* W = Wo + (size_t)(2 * kp) * D_ + n;
            uint32_t hi, lo; split2(W[0], W[D_], hi, lo);
            g_Wo_hi[w] = hi; g_Wo_lo[w] = lo;
        }
    }
}

// ---------------------------------------------------------------------------
// Kernel 0b: X prep -> packed words [b*S+s][dpair] (dedups the 12x split).
// ---------------------------------------------------------------------------
__global__ __launch_bounds__(256) void prep_x(const float* __restrict__ x)
{
    int idx = blockIdx.x * 256 + threadIdx.x;     // X_WORDS total
    int kp = idx & 255;
    int rs = idx >> 8;                             // b*S+s
    float2 v = *(const float2*)&x[(size_t)rs * D_ + 2 * kp];
    uint32_t hi, lo; split2(v.x, v.y, hi, lo);
    g_Xhi[idx] = hi; g_Xlo[idx] = lo;
}

// ---------------------------------------------------------------------------
// Kernel 0c: V transpose (once): [bh][s][dkpair] -> [bh][dk][spair].
// grid (8 s-tiles of 64, 256 bh), block 256, smem-tiled.
// ---------------------------------------------------------------------------
__global__ __launch_bounds__(256) void transpose_v()
{
    __shared__ uint32_t th[32 * 66];   // [kp][s_local], pad 2
    __shared__ uint32_t tl[32 * 66];
    const int bh = blockIdx.y;
    const int s0 = blockIdx.x * 64;
    const int t  = threadIdx.x;

    #pragma unroll
    for (int i = 0; i < 2; i++) {
        int c = t + 256 * i;
        int row = c >> 3, kq = (c & 7) * 4;
        uint4 v = *(const uint4*)&g_Vhi[((size_t)bh * S_ + s0 + row) * 32 + kq];
        th[(kq+0)*66 + row] = v.x; th[(kq+1)*66 + row] = v.y;
        th[(kq+2)*66 + row] = v.z; th[(kq+3)*66 + row] = v.w;
        v = *(const uint4*)&g_Vlo[((size_t)bh * S_ + s0 + row) * 32 + kq];
        tl[(kq+0)*66 + row] = v.x; tl[(kq+1)*66 + row] = v.y;
        tl[(kq+2)*66 + row] = v.z; tl[(kq+3)*66 + row] = v.w;
    }
    __syncthreads();

    const int spb = s0 >> 1;
    #pragma unroll
    for (int i = 0; i < 8; i++) {
        int c = t + 256 * i;
        int sp = c & 31, dk = c >> 5;
        int sel = (dk & 1) ? 0x7632 : 0x5410;  // pick hi/lo 16 of each source word
        uint2 a = *(const uint2*)&th[(dk >> 1) * 66 + 2 * sp];
        g_Vthi[((size_t)bh * DK_ + dk) * 256 + spb + sp] = __byte_perm(a.x, a.y, sel);
        uint2 bb = *(const uint2*)&tl[(dk >> 1) * 66 + 2 * sp];
        g_Vtlo[((size_t)bh * DK_ + dk) * 256 + spb + sp] = __byte_perm(bb.x, bb.y, sel);
    }
}

// ---------------------------------------------------------------------------
// Kernel 1: QKV projections, bf16x2 MMA, cp.async double-buffered.
// grid (4 s-tiles, 32 b, 12 = 3 mats x 4 head-pairs), block 256.
// Dyn smem: [2 buf][Xhi|Xlo|Whi|Wlo][128*20] = 20480 words = 80KB.
// ---------------------------------------------------------------------------
#define QKV_SMEM_WORDS (2*4*128*20)

__device__ __forceinline__ void qkv_prefetch(uint32_t* smw, int buf, int t,
                                             int b, int s0, int mat, int hp, int d0)
{
    uint32_t base = (uint32_t)__cvta_generic_to_shared(smw + buf * 10240);
    int dw = d0 >> 1;
    #pragma unroll
    for (int i = 0; i < 8; i++) {
        int c = t + 256 * i;
        int arr = c >> 9, rem = c & 511;
        int row = rem >> 2, c4 = (rem & 3) * 4;
        const uint32_t* src;
        if (arr == 0)      src = g_Xhi + ((size_t)(b * S_ + s0 + row)) * 256 + dw + c4;
        else if (arr == 1) src = g_Xlo + ((size_t)(b * S_ + s0 + row)) * 256 + dw + c4;
        else {
            int h = 2 * hp + (row >> 6), n = row & 63;
            size_t off = ((size_t)((mat * 8 + h) * 64 + n)) * 256 + dw + c4;
            src = ((arr == 2) ? g_Wqkv_hi : g_Wqkv_lo) + off;
        }
        cp16(base + (uint32_t)(arr * 2560 + row * 20 + c4) * 4, src);
    }
}

__global__ __launch_bounds__(256, 2) void qkv_mma(const float* __restrict__ bias)
{
    extern __shared__ uint32_t dynsm[];
    const int t    = threadIdx.x;
    const int warp = t >> 5, lane = t & 31;
    const int gid  = lane >> 2, tig = lane & 3;
    const int wrow = warp * 16;

    const int s0  = blockIdx.x * 128;
    const int b   = blockIdx.y;
    const int g   = blockIdx.z;
    const int mat = g >> 2;
    const int hp  = g & 3;

    uint32_t* Ohi = (mat == 0) ? g_Qhi : (mat == 1 ? g_Khi : g_Vhi);
    uint32_t* Olo = (mat == 0) ? g_Qlo : (mat == 1 ? g_Klo : g_Vlo);

    float acc[16][4];
    #pragma unroll
    for (int nt = 0; nt < 16; nt++) { acc[nt][0]=0.f; acc[nt][1]=0.f; acc[nt][2]=0.f; acc[nt][3]=0.f; }

    qkv_prefetch(dynsm, 0, t, b, s0, mat, hp, 0);
    CP_COMMIT();

    for (int it = 0; it < 16; it++) {
        if (it < 15) { qkv_prefetch(dynsm, (it + 1) & 1, t, b, s0, mat, hp, (it + 1) * 32); CP_COMMIT(); }
        if (it < 15) CP_WAIT1(); else CP_WAIT0();
        __syncthreads();

        uint32_t* Xh = dynsm + (it & 1) * 10240;
        uint32_t* Xl = Xh + 2560;
        uint32_t* Wh = Xh + 5120;
        uint32_t* Wl = Xh + 7680;

        #pragma unroll
        for (int ch = 0; ch < 2; ch++) {
            uint32_t ah0 = Xh[(wrow + gid)     * 20 + ch * 8 + tig];
            uint32_t ah1 = Xh[(wrow + gid + 8) * 20 + ch * 8 + tig];
            uint32_t ah2 = Xh[(wrow + gid)     * 20 + ch * 8 + tig + 4];
            uint32_t ah3 = Xh[(wrow + gid + 8) * 20 + ch * 8 + tig + 4];
            uint32_t al0 = Xl[(wrow + gid)     * 20 + ch * 8 + tig];
            uint32_t al1 = Xl[(wrow + gid + 8) * 20 + ch * 8 + tig];
            uint32_t al2 = Xl[(wrow + gid)     * 20 + ch * 8 + tig + 4];
            uint32_t al3 = Xl[(wrow + gid + 8) * 20 + ch * 8 + tig + 4];
            #pragma unroll
            for (int nt = 0; nt < 16; nt++) {
                uint32_t bh0 = Wh[(nt * 8 + gid) * 20 + ch * 8 + tig];
                uint32_t bh1 = Wh[(nt * 8 + gid) * 20 + ch * 8 + tig + 4];
                uint32_t bl0 = Wl[(nt * 8 + gid) * 20 + ch * 8 + tig];
                uint32_t bl1 = Wl[(nt * 8 + gid) * 20 + ch * 8 + tig + 4];
                mma16(acc[nt], ah0, ah1, ah2, ah3, bh0, bh1);
                mma16(acc[nt], ah0, ah1, ah2, ah3, bl0, bl1);
                mma16(acc[nt], al0, al1, al2, al3, bh0, bh1);
            }
        }
        __syncthreads();
    }

    const float bs = bias[0];
    const int row0 = s0 + wrow + gid;
    #pragma unroll
    for (int nt = 0; nt < 16; nt++) {
        int col = nt * 8 + 2 * tig;
        int hh  = col >> 6;
        int dkp = (col & 63) >> 1;
        size_t base = ((size_t)(b * H_ + 2 * hp + hh) * S_);
        uint32_t hi0, lo0, hi1, lo1;
        split2(acc[nt][0] + bs, acc[nt][1] + bs, hi0, lo0);
        split2(acc[nt][2] + bs, acc[nt][3] + bs, hi1, lo1);
        Ohi[(base + row0)     * 32 + dkp] = hi0;  Olo[(base + row0)     * 32 + dkp] = lo0;
        Ohi[(base + row0 + 8) * 32 + dkp] = hi1;  Olo[(base + row0 + 8) * 32 + dkp] = lo1;
    }
}

// ---------------------------------------------------------------------------
// Kernel 2: fused attention. cp.async double-buffered K/V^T tiles,
// Q frags + P words register-resident (no P smem round-trip).
// grid (4 q-tiles, 256 bh), block 256.
// Dyn smem: [2][Khi|Klo|Vthi|Vtlo][64*36] + mask int[2][64] = 18560 words.
// ---------------------------------------------------------------------------
#define ATTN_SMEM_WORDS (2*4*64*36 + 2*64)

__device__ __forceinline__ void attn_prefetch(uint32_t* smw, int buf, int t,
                                              int bh, int b, int t0,
                                              const int* __restrict__ mask)
{
    uint32_t base = (uint32_t)__cvta_generic_to_shared(smw + buf * 9216);
    #pragma unroll
    for (int i = 0; i < 8; i++) {
        int c = t + 256 * i;
        int arr = c >> 9, rem = c & 511;
        int row = rem >> 3, c4 = (rem & 7) * 4;
        const uint32_t* src;
        if (arr == 0)      src = g_Khi  + ((size_t)bh * S_ + t0 + row) * 32 + c4;
        else if (arr == 1) src = g_Klo  + ((size_t)bh * S_ + t0 + row) * 32 + c4;
        else if (arr == 2) src = g_Vthi + ((size_t)bh * DK_ + row) * 256 + (t0 >> 1) + c4;
        else               src = g_Vtlo + ((size_t)bh * DK_ + row) * 256 + (t0 >> 1) + c4;
        cp16(base + (uint32_t)(arr * 2304 + row * 36 + c4) * 4, src);
    }
    if (t < 16) {
        uint32_t mb = (uint32_t)__cvta_generic_to_shared(smw + 18432 + buf * 64);
        cp16(mb + t * 16, mask + b * S_ + t0 + t * 4);
    }
}

__global__ __launch_bounds__(256, 1) void attn_mma(const int* __restrict__ mask)
{
    extern __shared__ uint32_t dynsm[];
    const int t    = threadIdx.x;
    const int warp = t >> 5, lane = t & 31;
    const int gid  = lane >> 2, tig = lane & 3;
    const int wrow = warp * 16;

    const int q0 = blockIdx.x * 128;
    const int bh = blockIdx.y;
    const int b  = bh >> 3, h = bh & 7;

    // Q fragments direct from global (one-time)
    uint32_t qh[4][4], ql[4][4];
    {
        const uint32_t* q0h = g_Qhi + ((size_t)bh * S_ + q0 + wrow + gid) * 32;
        const uint32_t* q1h = q0h + 8 * 32;
        const uint32_t* q0l = g_Qlo + ((size_t)bh * S_ + q0 + wrow + gid) * 32;
        const uint32_t* q1l = q0l + 8 * 32;
        #pragma unroll
        for (int c = 0; c < 4; c++) {
            qh[c][0] = q0h[c * 8 + tig];     qh[c][1] = q1h[c * 8 + tig];
            qh[c][2] = q0h[c * 8 + tig + 4]; qh[c][3] = q1h[c * 8 + tig + 4];
            ql[c][0] = q0l[c * 8 + tig];     ql[c][1] = q1l[c * 8 + tig];
            ql[c][2] = q0l[c * 8 + tig + 4]; ql[c][3] = q1l[c * 8 + tig + 4];
        }
    }

    float o[8][4];
    #pragma unroll
    for (int nt = 0; nt < 8; nt++) { o[nt][0]=0.f; o[nt][1]=0.f; o[nt][2]=0.f; o[nt][3]=0.f; }
    float m0 = __int_as_float(0xff800000), m1 = m0;
    float l0 = 0.f, l1 = 0.f;

    attn_prefetch(dynsm, 0, t, bh, b, 0, mask);
    CP_COMMIT();

    for (int it = 0; it < 8; it++) {
        if (it < 7) { attn_prefetch(dynsm, (it + 1) & 1, t, bh, b, (it + 1) * 64, mask); CP_COMMIT(); }
        if (it < 7) CP_WAIT1(); else CP_WAIT0();
        __syncthreads();

        uint32_t* Kh = dynsm + (it & 1) * 9216;
        uint32_t* Kl = Kh + 2304;
        uint32_t* Vh = Kh + 4608;
        uint32_t* Vl = Kh + 6912;
        const int* mki = (const int*)(dynsm + 18432 + (it & 1) * 64);

        // Scores: S[128 x 64] = Q K^T (3-term)
        float s[8][4];
        #pragma unroll
        for (int nt = 0; nt < 8; nt++) { s[nt][0]=0.f; s[nt][1]=0.f; s[nt][2]=0.f; s[nt][3]=0.f; }
        #pragma unroll
        for (int ch = 0; ch < 4; ch++) {
            #pragma unroll
            for (int nt = 0; nt < 8; nt++) {
                uint32_t bh0 = Kh[(nt * 8 + gid) * 36 + ch * 8 + tig];
                uint32_t bh1 = Kh[(nt * 8 + gid) * 36 + ch * 8 + tig + 4];
                uint32_t bl0 = Kl[(nt * 8 + gid) * 36 + ch * 8 + tig];
                uint32_t bl1 = Kl[(nt * 8 + gid) * 36 + ch * 8 + tig + 4];
                mma16(s[nt], qh[ch][0], qh[ch][1], qh[ch][2], qh[ch][3], bh0, bh1);
                mma16(s[nt], qh[ch][0], qh[ch][1], qh[ch][2], qh[ch][3], bl0, bl1);
                mma16(s[nt], ql[ch][0], ql[ch][1], ql[ch][2], ql[ch][3], bh0, bh1);
            }
        }

        // Scale + mask
        #pragma unroll
        for (int nt = 0; nt < 8; nt++) {
            int col = nt * 8 + 2 * tig;
            int mk0 = mki[col], mk1 = mki[col + 1];
            s[nt][0] = mk0 ? s[nt][0] * 0.125f : NEG_INF_;
            s[nt][1] = mk1 ? s[nt][1] * 0.125f : NEG_INF_;
            s[nt][2] = mk0 ? s[nt][2] * 0.125f : NEG_INF_;
            s[nt][3] = mk1 ? s[nt][3] * 0.125f : NEG_INF_;
        }

        // Row maxes (quad reduction)
        float ml0 = fmaxf(s[0][0], s[0][1]), ml1 = fmaxf(s[0][2], s[0][3]);
        #pragma unroll
        for (int nt = 1; nt < 8; nt++) {
            ml0 = fmaxf(ml0, fmaxf(s[nt][0], s[nt][1]));
            ml1 = fmaxf(ml1, fmaxf(s[nt][2], s[nt][3]));
        }
        ml0 = fmaxf(ml0, __shfl_xor_sync(0xffffffffu, ml0, 1));
        ml0 = fmaxf(ml0, __shfl_xor_sync(0xffffffffu, ml0, 2));
        ml1 = fmaxf(ml1, __shfl_xor_sync(0xffffffffu, ml1, 1));
        ml1 = fmaxf(ml1, __shfl_xor_sync(0xffffffffu, ml1, 2));

        float mn0 = fmaxf(m0, ml0), mn1 = fmaxf(m1, ml1);
        float c0 = __expf(m0 - mn0), c1 = __expf(m1 - mn1);
        m0 = mn0; m1 = mn1;
        #pragma unroll
        for (int nt = 0; nt < 8; nt++) {
            o[nt][0] *= c0; o[nt][1] *= c0;
            o[nt][2] *= c1; o[nt][3] *= c1;
        }

        // Exponentiate -> P words in REGISTERS (lane owns exactly its PV A-frags)
        uint32_t phr0[8], plr0[8], phr1[8], plr1[8];
        float ps0 = 0.f, ps1 = 0.f;
        #pragma unroll
        for (int nt = 0; nt < 8; nt++) {
            float p00 = __expf(s[nt][0] - m0);
            float p01 = __expf(s[nt][1] - m0);
            float p10 = __expf(s[nt][2] - m1);
            float p11 = __expf(s[nt][3] - m1);
            ps0 += p00 + p01; ps1 += p10 + p11;
            split2(p00, p01, phr0[nt], plr0[nt]);
            split2(p10, p11, phr1[nt], plr1[nt]);
        }
        ps0 += __shfl_xor_sync(0xffffffffu, ps0, 1);
        ps0 += __shfl_xor_sync(0xffffffffu, ps0, 2);
        ps1 += __shfl_xor_sync(0xffffffffu, ps1, 1);
        ps1 += __shfl_xor_sync(0xffffffffu, ps1, 2);
        l0 = l0 * c0 + ps0;
        l1 = l1 * c1 + ps1;

        // PV: O += P V (3-term), A from registers, B from V^T smem
        #pragma unroll
        for (int ch = 0; ch < 4; ch++) {
            uint32_t ah0 = phr0[2*ch],   ah1 = phr1[2*ch];
            uint32_t ah2 = phr0[2*ch+1], ah3 = phr1[2*ch+1];
            uint32_t al0 = plr0[2*ch],   al1 = plr1[2*ch];
            uint32_t al2 = plr0[2*ch+1], al3 = plr1[2*ch+1];
            #pragma unroll
            for (int nt = 0; nt < 8; nt++) {
                uint32_t bh0 = Vh[(nt * 8 + gid) * 36 + ch * 8 + tig];
                uint32_t bh1 = Vh[(nt * 8 + gid) * 36 + ch * 8 + tig + 4];
                uint32_t bl0 = Vl[(nt * 8 + gid) * 36 + ch * 8 + tig];
                uint32_t bl1 = Vl[(nt * 8 + gid) * 36 + ch * 8 + tig + 4];
                mma16(o[nt], ah0, ah1, ah2, ah3, bh0, bh1);
                mma16(o[nt], ah0, ah1, ah2, ah3, bl0, bl1);
                mma16(o[nt], al0, al1, al2, al3, bh0, bh1);
            }
        }
        __syncthreads();
    }

    const float inv0 = 1.f / l0, inv1 = 1.f / l1;
    const int q = q0 + wrow + gid;
    #pragma unroll
    for (int nt = 0; nt < 8; nt++) {
        int kp = nt * 4 + tig;
        uint32_t hi, lo;
        split2(o[nt][0] * inv0, o[nt][1] * inv0, hi, lo);
        g_Hhi[((size_t)(b * S_ + q)) * 256 + h * 32 + kp] = hi;
        g_Hlo[((size_t)(b * S_ + q)) * 256 + h * 32 + kp] = lo;
        split2(o[nt][2] * inv1, o[nt][3] * inv1, hi, lo);
        g_Hhi[((size_t)(b * S_ + q + 8)) * 256 + h * 32 + kp] = hi;
        g_Hlo[((size_t)(b * S_ + q + 8)) * 256 + h * 32 + kp] = lo;
    }
}

// ---------------------------------------------------------------------------
// Kernel 3: output projection, bf16x2 MMA, cp.async double-buffered.
// grid (128 m-tiles, 4 n-tiles), block 256.  Dyn smem = 80KB.
// ---------------------------------------------------------------------------
#define OUT_SMEM_WORDS (2*4*128*20)

__device__ __forceinline__ void out_prefetch(uint32_t* smw, int buf, int t,
                                             int m0, int n0, int d0)
{
    uint32_t base = (uint32_t)__cvta_generic_to_shared(smw + buf * 10240);
    int dw = d0 >> 1;
    #pragma unroll
    for (int i = 0; i < 8; i++) {
        int c = t + 256 * i;
        int arr = c >> 9, rem = c & 511;
        int row = rem >> 2, c4 = (rem & 3) * 4;
        const uint32_t* src;
        if (arr == 0)      src = g_Hhi   + (size_t)(m0 + row) * 256 + dw + c4;
        else if (arr == 1) src = g_Hlo   + (size_t)(m0 + row) * 256 + dw + c4;
        else if (arr == 2) src = g_Wo_hi + (size_t)(n0 + row) * 256 + dw + c4;
        else               src = g_Wo_lo + (size_t)(n0 + row) * 256 + dw + c4;
        cp16(base + (uint32_t)(arr * 2560 + row * 20 + c4) * 4, src);
    }
}

__global__ __launch_bounds__(256, 2) void out_mma(
    const float* __restrict__ bias, float* __restrict__ out)
{
    extern __shared__ uint32_t dynsm[];
    const int t    = threadIdx.x;
    const int warp = t >> 5, lane = t & 31;
    const int gid  = lane >> 2, tig = lane & 3;
    const int wrow = warp * 16;

    const int m0 = blockIdx.x * 128;
    const int n0 = blockIdx.y * 128;

    float acc[16][4];
    #pragma unroll
    for (int nt = 0; nt < 16; nt++) { acc[nt][0]=0.f; acc[nt][1]=0.f; acc[nt][2]=0.f; acc[nt][3]=0.f; }

    out_prefetch(dynsm, 0, t, m0, n0, 0);
    CP_COMMIT();

    for (int it = 0; it < 16; it++) {
        if (it < 15) { out_prefetch(dynsm, (it + 1) & 1, t, m0, n0, (it + 1) * 32); CP_COMMIT(); }
        if (it < 15) CP_WAIT1(); else CP_WAIT0();
        __syncthreads();

        uint32_t* Ah = dynsm + (it & 1) * 10240;
        uint32_t* Al = Ah + 2560;
        uint32_t* Bh = Ah + 5120;
        uint32_t* Bl = Ah + 7680;

        #pragma unroll
        for (int ch = 0; ch < 2; ch++) {
            uint32_t ah0 = Ah[(wrow + gid)     * 20 + ch * 8 + tig];
            uint32_t ah1 = Ah[(wrow + gid + 8) * 20 + ch * 8 + tig];
            uint32_t ah2 = Ah[(wrow + gid)     * 20 + ch * 8 + tig + 4];
            uint32_t ah3 = Ah[(wrow + gid + 8) * 20 + ch * 8 + tig + 4];
            uint32_t al0 = Al[(wrow + gid)     * 20 + ch * 8 + tig];
            uint32_t al1 = Al[(wrow + gid + 8) * 20 + ch * 8 + tig];
            uint32_t al2 = Al[(wrow + gid)     * 20 + ch * 8 + tig + 4];
            uint32_t al3 = Al[(wrow + gid + 8) * 20 + ch * 8 + tig + 4];
            #pragma unroll
            for (int nt = 0; nt < 16; nt++) {
                uint32_t bh0 = Bh[(nt * 8 + gid) * 20 + ch * 8 + tig];
                uint32_t bh1 = Bh[(nt * 8 + gid) * 20 + ch * 8 + tig + 4];
                uint32_t bl0 = Bl[(nt * 8 + gid) * 20 + ch * 8 + tig];
                uint32_t bl1 = Bl[(nt * 8 + gid) * 20 + ch * 8 + tig + 4];
                mma16(acc[nt], ah0, ah1, ah2, ah3, bh0, bh1);
                mma16(acc[nt], ah0, ah1, ah2, ah3, bl0, bl1);
                mma16(acc[nt], al0, al1, al2, al3, bh0, bh1);
            }
        }
        __syncthreads();
    }

    const float bs = bias[0];
    const int row0 = m0 + wrow + gid;
    #pragma unroll
    for (int nt = 0; nt < 16; nt++) {
        int col = n0 + nt * 8 + 2 * tig;
        *(float2*)&out[(size_t)row0 * D_ + col]       = make_float2(acc[nt][0] + bs, acc[nt][1] + bs);
        *(float2*)&out[(size_t)(row0 + 8) * D_ + col] = make_float2(acc[nt][2] + bs, acc[nt][3] + bs);
    }
}

// ---------------------------------------------------------------------------
extern "C" void kernel_launch(void* const* d_in, const int* in_sizes, int n_in,
                              void* d_out, int out_size)
{
    const float* x    = (const float*)d_in[0];
    const int*   mask = (const int*)  d_in[1];
    const float* Wq   = (const float*)d_in[2];
    const float* Wk   = (const float*)d_in[3];
    const float* Wv   = (const float*)d_in[4];
    const float* Wo   = (const float*)d_in[5];
    const float* bias = (const float*)d_in[6];
    float*       out  = (float*)d_out;

    static bool attr_set = false;
    if (!attr_set) {
        cudaFuncSetAttribute(qkv_mma,  cudaFuncAttributeMaxDynamicSharedMemorySize,
                             QKV_SMEM_WORDS  * (int)sizeof(uint32_t));
        cudaFuncSetAttribute(attn_mma, cudaFuncAttributeMaxDynamicSharedMemorySize,
                             ATTN_SMEM_WORDS * (int)sizeof(uint32_t));
        cudaFuncSetAttribute(out_mma,  cudaFuncAttributeMaxDynamicSharedMemorySize,
                             OUT_SMEM_WORDS  * (int)sizeof(uint32_t));
        attr_set = true;
    }

    prep_w<<<(WQKV_WORDS + WO_WORDS) / 256, 256>>>(Wq, Wk, Wv, Wo);
    prep_x<<<X_WORDS / 256, 256>>>(x);
    qkv_mma<<<dim3(4, 32, 12), 256, QKV_SMEM_WORDS * sizeof(uint32_t)>>>(bias);
    transpose_v<<<dim3(8, 256), 256>>>();
    attn_mma<<<dim3(4, 256), 256, ATTN_SMEM_WORDS * sizeof(uint32_t)>>>(mask);
    out_mma<<<dim3(128, 4), 256, OUT_SMEM_WORDS * sizeof(uint32_t)>>>(bias, out);
}

// round 15
// speedup vs baseline: 1.2742x; 1.0438x over previous
#include <cuda_runtime.h>
#include <cuda_bf16.h>
#include <cstdint>

#define B_  32
#define S_  512
#define D_  512
#define H_  8
#define DK_ 64
#define NEG_INF_ (-1e30f)

// ---------------------------------------------------------------------------
// Packed bf16-pair (u32 = 2 bf16 along K; even k in low 16) hi/lo split arrays.
// ---------------------------------------------------------------------------
#define WQKV_WORDS (3*8*64*256)          // [(mat*8+h)*64+n][kpair 0..255]
#define WO_WORDS   (512*256)             // [n 0..511][kpair 0..255]
#define X_WORDS    (B_*S_*256)           // [b*S+s][dpair 0..255]
#define QKV_WORDS  (B_*H_*S_*32)         // [bh][s][dkpair 0..31]
#define VT_WORDS   (B_*H_*DK_*256)       // [bh][dk][spair 0..255]
#define HH_WORDS   (B_*S_*H_*32)         // [b*S+s][256 words]

__device__ uint32_t g_Wqkv_hi[WQKV_WORDS], g_Wqkv_lo[WQKV_WORDS];
__device__ uint32_t g_Wo_hi[WO_WORDS],     g_Wo_lo[WO_WORDS];
__device__ uint32_t g_Xhi[X_WORDS],   g_Xlo[X_WORDS];
__device__ uint32_t g_Qhi[QKV_WORDS], g_Qlo[QKV_WORDS];
__device__ uint32_t g_Khi[QKV_WORDS], g_Klo[QKV_WORDS];
__device__ uint32_t g_Vhi[QKV_WORDS], g_Vlo[QKV_WORDS];
__device__ uint32_t g_Vthi[VT_WORDS], g_Vtlo[VT_WORDS];
__device__ uint32_t g_Hhi[HH_WORDS],  g_Hlo[HH_WORDS];

__device__ __forceinline__ uint32_t pack_bf2(float x0, float x1) {
    unsigned short u0 = __bfloat16_as_ushort(__float2bfloat16_rn(x0));
    unsigned short u1 = __bfloat16_as_ushort(__float2bfloat16_rn(x1));
    return ((uint32_t)u1 << 16) | (uint32_t)u0;
}
__device__ __forceinline__ void split2(float x0, float x1, uint32_t& hi, uint32_t& lo) {
    __nv_bfloat16 h0 = __float2bfloat16_rn(x0);
    __nv_bfloat16 h1 = __float2bfloat16_rn(x1);
    hi = ((uint32_t)__bfloat16_as_ushort(h1) << 16) | (uint32_t)__bfloat16_as_ushort(h0);
    lo = pack_bf2(x0 - __bfloat162float(h0), x1 - __bfloat162float(h1));
}

__device__ __forceinline__ void mma16(float* c,
    uint32_t a0, uint32_t a1, uint32_t a2, uint32_t a3,
    uint32_t b0, uint32_t b1)
{
    asm volatile(
        "mma.sync.aligned.m16n8k16.row.col.f32.bf16.bf16.f32 "
        "{%0,%1,%2,%3},{%4,%5,%6,%7},{%8,%9},{%0,%1,%2,%3};"
        : "+f"(c[0]), "+f"(c[1]), "+f"(c[2]), "+f"(c[3])
        : "r"(a0), "r"(a1), "r"(a2), "r"(a3), "r"(b0), "r"(b1));
}

// 4x m8n8 b16 matrices; lane l supplies row address for matrix (l>>3), row (l&7)
__device__ __forceinline__ void ldsm4(uint32_t addr, uint32_t* r) {
    asm volatile("ldmatrix.sync.aligned.m8n8.x4.shared.b16 {%0,%1,%2,%3}, [%4];"
        : "=r"(r[0]), "=r"(r[1]), "=r"(r[2]), "=r"(r[3]) : "r"(addr));
}

__device__ __forceinline__ void cp16(uint32_t dst_smem, const void* src) {
    asm volatile("cp.async.cg.shared.global [%0], [%1], 16;"
                 :: "r"(dst_smem), "l"(src));
}
#define CP_COMMIT() asm volatile("cp.async.commit_group;")
#define CP_WAIT1()  asm volatile("cp.async.wait_group 1;")
#define CP_WAIT0()  asm volatile("cp.async.wait_group 0;")

// ---------------------------------------------------------------------------
// Kernel 0a: weight prep -> [n-row][kpair] packed words.
// ---------------------------------------------------------------------------
__global__ __launch_bounds__(256) void prep_w(
    const float* __restrict__ Wq, const float* __restrict__ Wk,
    const float* __restrict__ Wv, const float* __restrict__ Wo)
{
    int idx = blockIdx.x * 256 + threadIdx.x;
    if (idx < WQKV_WORDS) {
        int kp = idx & 255;
        int r  = idx >> 8;
        int n  = r & 63;
        int h  = (r >> 6) & 7;
        int mat = r >> 9;
        const float* W = ((mat == 0) ? Wq : (mat == 1 ? Wk : Wv))
                       + ((size_t)h * D_ + 2 * kp) * DK_ + n;
        uint32_t hi, lo; split2(W[0], W[DK_], hi, lo);
        g_Wqkv_hi[idx] = hi; g_Wqkv_lo[idx] = lo;
    } else {
        int w = idx - WQKV_WORDS;
        if (w < WO_WORDS) {
            int kp = w & 255;
            int n  = w >> 8;
            const float* W = Wo + (size_t)(2 * kp) * D_ + n;
            uint32_t hi, lo; split2(W[0], W[D_], hi, lo);
            g_Wo_hi[w] = hi; g_Wo_lo[w] = lo;
        }
    }
}

// ---------------------------------------------------------------------------
// Kernel 0b: X prep -> packed words [b*S+s][dpair].
// ---------------------------------------------------------------------------
__global__ __launch_bounds__(256) void prep_x(const float* __restrict__ x)
{
    int idx = blockIdx.x * 256 + threadIdx.x;
    int kp = idx & 255;
    int rs = idx >> 8;
    float2 v = *(const float2*)&x[(size_t)rs * D_ + 2 * kp];
    uint32_t hi, lo; split2(v.x, v.y, hi, lo);
    g_Xhi[idx] = hi; g_Xlo[idx] = lo;
}

// ---------------------------------------------------------------------------
// Kernel 0c: V transpose (once): [bh][s][dkpair] -> [bh][dk][spair].
// ---------------------------------------------------------------------------
__global__ __launch_bounds__(256) void transpose_v()
{
    __shared__ uint32_t th[32 * 66];
    __shared__ uint32_t tl[32 * 66];
    const int bh = blockIdx.y;
    const int s0 = blockIdx.x * 64;
    const int t  = threadIdx.x;

    #pragma unroll
    for (int i = 0; i < 2; i++) {
        int c = t + 256 * i;
        int row = c >> 3, kq = (c & 7) * 4;
        uint4 v = *(const uint4*)&g_Vhi[((size_t)bh * S_ + s0 + row) * 32 + kq];
        th[(kq+0)*66 + row] = v.x; th[(kq+1)*66 + row] = v.y;
        th[(kq+2)*66 + row] = v.z; th[(kq+3)*66 + row] = v.w;
        v = *(const uint4*)&g_Vlo[((size_t)bh * S_ + s0 + row) * 32 + kq];
        tl[(kq+0)*66 + row] = v.x; tl[(kq+1)*66 + row] = v.y;
        tl[(kq+2)*66 + row] = v.z; tl[(kq+3)*66 + row] = v.w;
    }
    __syncthreads();

    const int spb = s0 >> 1;
    #pragma unroll
    for (int i = 0; i < 8; i++) {
        int c = t + 256 * i;
        int sp = c & 31, dk = c >> 5;
        int sel = (dk & 1) ? 0x7632 : 0x5410;
        uint2 a = *(const uint2*)&th[(dk >> 1) * 66 + 2 * sp];
        g_Vthi[((size_t)bh * DK_ + dk) * 256 + spb + sp] = __byte_perm(a.x, a.y, sel);
        uint2 bb = *(const uint2*)&tl[(dk >> 1) * 66 + 2 * sp];
        g_Vtlo[((size_t)bh * DK_ + dk) * 256 + spb + sp] = __byte_perm(bb.x, bb.y, sel);
    }
}

// ---------------------------------------------------------------------------
// Kernel 1: QKV projections. 32x64 warp tiles + ldmatrix, cp.async pipelined.
// grid (4 s-tiles, 32 b, 12), block 256 = 4 m-warps x 2 n-warps.
// Dyn smem: [2 buf][Xhi|Xlo|Whi|Wlo][128*20] = 80KB.
// ---------------------------------------------------------------------------
#define QKV_SMEM_WORDS (2*4*128*20)

__device__ __forceinline__ void qkv_prefetch(uint32_t* smw, int buf, int t,
                                             int b, int s0, int mat, int hp, int d0)
{
    uint32_t base = (uint32_t)__cvta_generic_to_shared(smw + buf * 10240);
    int dw = d0 >> 1;
    #pragma unroll
    for (int i = 0; i < 8; i++) {
        int c = t + 256 * i;
        int arr = c >> 9, rem = c & 511;
        int row = rem >> 2, c4 = (rem & 3) * 4;
        const uint32_t* src;
        if (arr == 0)      src = g_Xhi + ((size_t)(b * S_ + s0 + row)) * 256 + dw + c4;
        else if (arr == 1) src = g_Xlo + ((size_t)(b * S_ + s0 + row)) * 256 + dw + c4;
        else {
            int h = 2 * hp + (row >> 6), n = row & 63;
            size_t off = ((size_t)((mat * 8 + h) * 64 + n)) * 256 + dw + c4;
            src = ((arr == 2) ? g_Wqkv_hi : g_Wqkv_lo) + off;
        }
        cp16(base + (uint32_t)(arr * 2560 + row * 20 + c4) * 4, src);
    }
}

__global__ __launch_bounds__(256, 2) void qkv_mma(const float* __restrict__ bias)
{
    extern __shared__ uint32_t dynsm[];
    const int t    = threadIdx.x;
    const int warp = t >> 5, lane = t & 31;
    const int gid  = lane >> 2, tig = lane & 3;
    const int wm   = warp >> 1, wn = warp & 1;

    const int s0  = blockIdx.x * 128;
    const int b   = blockIdx.y;
    const int g   = blockIdx.z;
    const int mat = g >> 2;
    const int hp  = g & 3;

    uint32_t* Ohi = (mat == 0) ? g_Qhi : (mat == 1 ? g_Khi : g_Vhi);
    uint32_t* Olo = (mat == 0) ? g_Qlo : (mat == 1 ? g_Klo : g_Vlo);

    // ldmatrix lane geometry (word offsets within an array, excl. ch)
    const int r8 = lane & 7;
    const int aRow = (((lane >> 3) & 1) << 3) + r8;   // row in m16
    const int aKq  = (lane >> 4) << 2;                // kpair quad
    const int bNt  = lane >> 4;                       // nt within pair
    const int bKq  = ((lane >> 3) & 1) << 2;
    int aoff[2], boff[4];
    #pragma unroll
    for (int mt = 0; mt < 2; mt++)
        aoff[mt] = (wm * 32 + mt * 16 + aRow) * 20 + aKq;
    #pragma unroll
    for (int np = 0; np < 4; np++)
        boff[np] = (wn * 64 + (np * 2 + bNt) * 8 + r8) * 20 + bKq;

    const uint32_t smb = (uint32_t)__cvta_generic_to_shared(dynsm);

    float acc[2][8][4];
    #pragma unroll
    for (int mt = 0; mt < 2; mt++)
        #pragma unroll
        for (int nt = 0; nt < 8; nt++) { acc[mt][nt][0]=0.f; acc[mt][nt][1]=0.f; acc[mt][nt][2]=0.f; acc[mt][nt][3]=0.f; }

    qkv_prefetch(dynsm, 0, t, b, s0, mat, hp, 0);
    CP_COMMIT();

    for (int it = 0; it < 16; it++) {
        if (it < 15) { qkv_prefetch(dynsm, (it + 1) & 1, t, b, s0, mat, hp, (it + 1) * 32); CP_COMMIT(); }
        if (it < 15) CP_WAIT1(); else CP_WAIT0();
        __syncthreads();

        uint32_t sb = smb + (uint32_t)((it & 1) * 10240) * 4;

        #pragma unroll
        for (int ch = 0; ch < 2; ch++) {
            uint32_t ah[2][4], al[2][4];
            ldsm4(sb + (uint32_t)(aoff[0] + ch * 8) * 4, ah[0]);
            ldsm4(sb + (uint32_t)(aoff[1] + ch * 8) * 4, ah[1]);
            ldsm4(sb + (uint32_t)(2560 + aoff[0] + ch * 8) * 4, al[0]);
            ldsm4(sb + (uint32_t)(2560 + aoff[1] + ch * 8) * 4, al[1]);
            #pragma unroll
            for (int np = 0; np < 4; np++) {
                uint32_t bh[4], bl[4];
                ldsm4(sb + (uint32_t)(5120 + boff[np] + ch * 8) * 4, bh);
                ldsm4(sb + (uint32_t)(7680 + boff[np] + ch * 8) * 4, bl);
                #pragma unroll
                for (int sub = 0; sub < 2; sub++) {
                    int nt = np * 2 + sub;
                    #pragma unroll
                    for (int mt = 0; mt < 2; mt++) {
                        mma16(acc[mt][nt], ah[mt][0], ah[mt][1], ah[mt][2], ah[mt][3], bh[2*sub], bh[2*sub+1]);
                        mma16(acc[mt][nt], ah[mt][0], ah[mt][1], ah[mt][2], ah[mt][3], bl[2*sub], bl[2*sub+1]);
                        mma16(acc[mt][nt], al[mt][0], al[mt][1], al[mt][2], al[mt][3], bh[2*sub], bh[2*sub+1]);
                    }
                }
            }
        }
        __syncthreads();
    }

    const float bs = bias[0];
    const size_t base = (size_t)(b * H_ + 2 * hp + wn) * S_;
    #pragma unroll
    for (int mt = 0; mt < 2; mt++) {
        int r = s0 + wm * 32 + mt * 16 + gid;
        #pragma unroll
        for (int nt = 0; nt < 8; nt++) {
            int dkp = nt * 4 + tig;
            uint32_t hi0, lo0, hi1, lo1;
            split2(acc[mt][nt][0] + bs, acc[mt][nt][1] + bs, hi0, lo0);
            split2(acc[mt][nt][2] + bs, acc[mt][nt][3] + bs, hi1, lo1);
            Ohi[(base + r)     * 32 + dkp] = hi0;  Olo[(base + r)     * 32 + dkp] = lo0;
            Ohi[(base + r + 8) * 32 + dkp] = hi1;  Olo[(base + r + 8) * 32 + dkp] = lo1;
        }
    }
}

// ---------------------------------------------------------------------------
// Kernel 2: fused attention. ldmatrix B-frags, P/Q register-resident,
// cp.async double-buffered.  grid (4 q-tiles, 256 bh), block 256.
// ---------------------------------------------------------------------------
#define ATTN_SMEM_WORDS (2*4*64*36 + 2*64)

__device__ __forceinline__ void attn_prefetch(uint32_t* smw, int buf, int t,
                                              int bh, int b, int t0,
                                              const int* __restrict__ mask)
{
    uint32_t base = (uint32_t)__cvta_generic_to_shared(smw + buf * 9216);
    #pragma unroll
    for (int i = 0; i < 8; i++) {
        int c = t + 256 * i;
        int arr = c >> 9, rem = c & 511;
        int row = rem >> 3, c4 = (rem & 7) * 4;
        const uint32_t* src;
        if (arr == 0)      src = g_Khi  + ((size_t)bh * S_ + t0 + row) * 32 + c4;
        else if (arr == 1) src = g_Klo  + ((size_t)bh * S_ + t0 + row) * 32 + c4;
        else if (arr == 2) src = g_Vthi + ((size_t)bh * DK_ + row) * 256 + (t0 >> 1) + c4;
        else               src = g_Vtlo + ((size_t)bh * DK_ + row) * 256 + (t0 >> 1) + c4;
        cp16(base + (uint32_t)(arr * 2304 + row * 36 + c4) * 4, src);
    }
    if (t < 16) {
        uint32_t mb = (uint32_t)__cvta_generic_to_shared(smw + 18432 + buf * 64);
        cp16(mb + t * 16, mask + b * S_ + t0 + t * 4);
    }
}

__global__ __launch_bounds__(256, 1) void attn_mma(const int* __restrict__ mask)
{
    extern __shared__ uint32_t dynsm[];
    const int t    = threadIdx.x;
    const int warp = t >> 5, lane = t & 31;
    const int gid  = lane >> 2, tig = lane & 3;
    const int wrow = warp * 16;

    const int q0 = blockIdx.x * 128;
    const int bh = blockIdx.y;
    const int b  = bh >> 3, h = bh & 7;

    // ldmatrix B geometry (stride 36)
    const int r8 = lane & 7;
    const int bNt = lane >> 4;
    const int bKq = ((lane >> 3) & 1) << 2;
    int boff[4];
    #pragma unroll
    for (int np = 0; np < 4; np++)
        boff[np] = ((np * 2 + bNt) * 8 + r8) * 36 + bKq;

    const uint32_t smb = (uint32_t)__cvta_generic_to_shared(dynsm);

    // Q fragments direct from global (one-time)
    uint32_t qh[4][4], ql[4][4];
    {
        const uint32_t* q0h = g_Qhi + ((size_t)bh * S_ + q0 + wrow + gid) * 32;
        const uint32_t* q1h = q0h + 8 * 32;
        const uint32_t* q0l = g_Qlo + ((size_t)bh * S_ + q0 + wrow + gid) * 32;
        const uint32_t* q1l = q0l + 8 * 32;
        #pragma unroll
        for (int c = 0; c < 4; c++) {
            qh[c][0] = q0h[c * 8 + tig];     qh[c][1] = q1h[c * 8 + tig];
            qh[c][2] = q0h[c * 8 + tig + 4]; qh[c][3] = q1h[c * 8 + tig + 4];
            ql[c][0] = q0l[c * 8 + tig];     ql[c][1] = q1l[c * 8 + tig];
            ql[c][2] = q0l[c * 8 + tig + 4]; ql[c][3] = q1l[c * 8 + tig + 4];
        }
    }

    float o[8][4];
    #pragma unroll
    for (int nt = 0; nt < 8; nt++) { o[nt][0]=0.f; o[nt][1]=0.f; o[nt][2]=0.f; o[nt][3]=0.f; }
    float m0 = __int_as_float(0xff800000), m1 = m0;
    float l0 = 0.f, l1 = 0.f;

    attn_prefetch(dynsm, 0, t, bh, b, 0, mask);
    CP_COMMIT();

    for (int it = 0; it < 8; it++) {
        if (it < 7) { attn_prefetch(dynsm, (it + 1) & 1, t, bh, b, (it + 1) * 64, mask); CP_COMMIT(); }
        if (it < 7) CP_WAIT1(); else CP_WAIT0();
        __syncthreads();

        uint32_t sb = smb + (uint32_t)((it & 1) * 9216) * 4;
        const int* mki = (const int*)(dynsm + 18432 + (it & 1) * 64);

        // Scores: S[128 x 64] = Q K^T (3-term), B via ldmatrix
        float s[8][4];
        #pragma unroll
        for (int nt = 0; nt < 8; nt++) { s[nt][0]=0.f; s[nt][1]=0.f; s[nt][2]=0.f; s[nt][3]=0.f; }
        #pragma unroll
        for (int ch = 0; ch < 4; ch++) {
            #pragma unroll
            for (int np = 0; np < 4; np++) {
                uint32_t kh[4], kl[4];
                ldsm4(sb + (uint32_t)(boff[np] + ch * 8) * 4, kh);
                ldsm4(sb + (uint32_t)(2304 + boff[np] + ch * 8) * 4, kl);
                #pragma unroll
                for (int sub = 0; sub < 2; sub++) {
                    int nt = np * 2 + sub;
                    mma16(s[nt], qh[ch][0], qh[ch][1], qh[ch][2], qh[ch][3], kh[2*sub], kh[2*sub+1]);
                    mma16(s[nt], qh[ch][0], qh[ch][1], qh[ch][2], qh[ch][3], kl[2*sub], kl[2*sub+1]);
                    mma16(s[nt], ql[ch][0], ql[ch][1], ql[ch][2], ql[ch][3], kh[2*sub], kh[2*sub+1]);
                }
            }
        }

        // Scale + mask
        #pragma unroll
        for (int nt = 0; nt < 8; nt++) {
            int col = nt * 8 + 2 * tig;
            int mk0 = mki[col], mk1 = mki[col + 1];
            s[nt][0] = mk0 ? s[nt][0] * 0.125f : NEG_INF_;
            s[nt][1] = mk1 ? s[nt][1] * 0.125f : NEG_INF_;
            s[nt][2] = mk0 ? s[nt][2] * 0.125f : NEG_INF_;
            s[nt][3] = mk1 ? s[nt][3] * 0.125f : NEG_INF_;
        }

        // Row maxes (quad reduction)
        float ml0 = fmaxf(s[0][0], s[0][1]), ml1 = fmaxf(s[0][2], s[0][3]);
        #pragma unroll
        for (int nt = 1; nt < 8; nt++) {
            ml0 = fmaxf(ml0, fmaxf(s[nt][0], s[nt][1]));
            ml1 = fmaxf(ml1, fmaxf(s[nt][2], s[nt][3]));
        }
        ml0 = fmaxf(ml0, __shfl_xor_sync(0xffffffffu, ml0, 1));
        ml0 = fmaxf(ml0, __shfl_xor_sync(0xffffffffu, ml0, 2));
        ml1 = fmaxf(ml1, __shfl_xor_sync(0xffffffffu, ml1, 1));
        ml1 = fmaxf(ml1, __shfl_xor_sync(0xffffffffu, ml1, 2));

        float mn0 = fmaxf(m0, ml0), mn1 = fmaxf(m1, ml1);
        float c0 = __expf(m0 - mn0), c1 = __expf(m1 - mn1);
        m0 = mn0; m1 = mn1;
        #pragma unroll
        for (int nt = 0; nt < 8; nt++) {
            o[nt][0] *= c0; o[nt][1] *= c0;
            o[nt][2] *= c1; o[nt][3] *= c1;
        }

        // Exponentiate -> P words in registers
        uint32_t phr0[8], plr0[8], phr1[8], plr1[8];
        float ps0 = 0.f, ps1 = 0.f;
        #pragma unroll
        for (int nt = 0; nt < 8; nt++) {
            float p00 = __expf(s[nt][0] - m0);
            float p01 = __expf(s[nt][1] - m0);
            float p10 = __expf(s[nt][2] - m1);
            float p11 = __expf(s[nt][3] - m1);
            ps0 += p00 + p01; ps1 += p10 + p11;
            split2(p00, p01, phr0[nt], plr0[nt]);
            split2(p10, p11, phr1[nt], plr1[nt]);
        }
        ps0 += __shfl_xor_sync(0xffffffffu, ps0, 1);
        ps0 += __shfl_xor_sync(0xffffffffu, ps0, 2);
        ps1 += __shfl_xor_sync(0xffffffffu, ps1, 1);
        ps1 += __shfl_xor_sync(0xffffffffu, ps1, 2);
        l0 = l0 * c0 + ps0;
        l1 = l1 * c1 + ps1;

        // PV: O += P V (3-term), A regs, B via ldmatrix from V^T
        #pragma unroll
        for (int ch = 0; ch < 4; ch++) {
            uint32_t ah0 = phr0[2*ch],   ah1 = phr1[2*ch];
            uint32_t ah2 = phr0[2*ch+1], ah3 = phr1[2*ch+1];
            uint32_t al0 = plr0[2*ch],   al1 = plr1[2*ch];
            uint32_t al2 = plr0[2*ch+1], al3 = plr1[2*ch+1];
            #pragma unroll
            for (int np = 0; np < 4; np++) {
                uint32_t vh[4], vl[4];
                ldsm4(sb + (uint32_t)(4608 + boff[np] + ch * 8) * 4, vh);
                ldsm4(sb + (uint32_t)(6912 + boff[np] + ch * 8) * 4, vl);
                #pragma unroll
                for (int sub = 0; sub < 2; sub++) {
                    int nt = np * 2 + sub;
                    mma16(o[nt], ah0, ah1, ah2, ah3, vh[2*sub], vh[2*sub+1]);
                    mma16(o[nt], ah0, ah1, ah2, ah3, vl[2*sub], vl[2*sub+1]);
                    mma16(o[nt], al0, al1, al2, al3, vh[2*sub], vh[2*sub+1]);
                }
            }
        }
        __syncthreads();
    }

    const float inv0 = 1.f / l0, inv1 = 1.f / l1;
    const int q = q0 + wrow + gid;
    #pragma unroll
    for (int nt = 0; nt < 8; nt++) {
        int kp = nt * 4 + tig;
        uint32_t hi, lo;
        split2(o[nt][0] * inv0, o[nt][1] * inv0, hi, lo);
        g_Hhi[((size_t)(b * S_ + q)) * 256 + h * 32 + kp] = hi;
        g_Hlo[((size_t)(b * S_ + q)) * 256 + h * 32 + kp] = lo;
        split2(o[nt][2] * inv1, o[nt][3] * inv1, hi, lo);
        g_Hhi[((size_t)(b * S_ + q + 8)) * 256 + h * 32 + kp] = hi;
        g_Hlo[((size_t)(b * S_ + q + 8)) * 256 + h * 32 + kp] = lo;
    }
}

// ---------------------------------------------------------------------------
// Kernel 3: output projection. 32x64 warp tiles + ldmatrix, pipelined.
// grid (128 m-tiles, 4 n-tiles), block 256.
// ---------------------------------------------------------------------------
#define OUT_SMEM_WORDS (2*4*128*20)

__device__ __forceinline__ void out_prefetch(uint32_t* smw, int buf, int t,
                                             int m0, int n0, int d0)
{
    uint32_t base = (uint32_t)__cvta_generic_to_shared(smw + buf * 10240);
    int dw = d0 >> 1;
    #pragma unroll
    for (int i = 0; i < 8; i++) {
        int c = t + 256 * i;
        int arr = c >> 9, rem = c & 511;
        int row = rem >> 2, c4 = (rem & 3) * 4;
        const uint32_t* src;
        if (arr == 0)      src = g_Hhi   + (size_t)(m0 + row) * 256 + dw + c4;
        else if (arr == 1) src = g_Hlo   + (size_t)(m0 + row) * 256 + dw + c4;
        else if (arr == 2) src = g_Wo_hi + (size_t)(n0 + row) * 256 + dw + c4;
        else               src = g_Wo_lo + (size_t)(n0 + row) * 256 + dw + c4;
        cp16(base + (uint32_t)(arr * 2560 + row * 20 + c4) * 4, src);
    }
}

__global__ __launch_bounds__(256, 2) void out_mma(
    const float* __restrict__ bias, float* __restrict__ out)
{
    extern __shared__ uint32_t dynsm[];
    const int t    = threadIdx.x;
    const int warp = t >> 5, lane = t & 31;
    const int gid  = lane >> 2, tig = lane & 3;
    const int wm   = warp >> 1, wn = warp & 1;

    const int m0 = blockIdx.x * 128;
    const int n0 = blockIdx.y * 128;

    const int r8 = lane & 7;
    const int aRow = (((lane >> 3) & 1) << 3) + r8;
    const int aKq  = (lane >> 4) << 2;
    const int bNt  = lane >> 4;
    const int bKq  = ((lane >> 3) & 1) << 2;
    int aoff[2], boff[4];
    #pragma unroll
    for (int mt = 0; mt < 2; mt++)
        aoff[mt] = (wm * 32 + mt * 16 + aRow) * 20 + aKq;
    #pragma unroll
    for (int np = 0; np < 4; np++)
        boff[np] = (wn * 64 + (np * 2 + bNt) * 8 + r8) * 20 + bKq;

    const uint32_t smb = (uint32_t)__cvta_generic_to_shared(dynsm);

    float acc[2][8][4];
    #pragma unroll
    for (int mt = 0; mt < 2; mt++)
        #pragma unroll
        for (int nt = 0; nt < 8; nt++) { acc[mt][nt][0]=0.f; acc[mt][nt][1]=0.f; acc[mt][nt][2]=0.f; acc[mt][nt][3]=0.f; }

    out_prefetch(dynsm, 0, t, m0, n0, 0);
    CP_COMMIT();

    for (int it = 0; it < 16; it++) {
        if (it < 15) { out_prefetch(dynsm, (it + 1) & 1, t, m0, n0, (it + 1) * 32); CP_COMMIT(); }
        if (it < 15) CP_WAIT1(); else CP_WAIT0();
        __syncthreads();

        uint32_t sb = smb + (uint32_t)((it & 1) * 10240) * 4;

        #pragma unroll
        for (int ch = 0; ch < 2; ch++) {
            uint32_t ah[2][4], al[2][4];
            ldsm4(sb + (uint32_t)(aoff[0] + ch * 8) * 4, ah[0]);
            ldsm4(sb + (uint32_t)(aoff[1] + ch * 8) * 4, ah[1]);
            ldsm4(sb + (uint32_t)(2560 + aoff[0] + ch * 8) * 4, al[0]);
            ldsm4(sb + (uint32_t)(2560 + aoff[1] + ch * 8) * 4, al[1]);
            #pragma unroll
            for (int np = 0; np < 4; np++) {
                uint32_t bh[4], bl[4];
                ldsm4(sb + (uint32_t)(5120 + boff[np] + ch * 8) * 4, bh);
                ldsm4(sb + (uint32_t)(7680 + boff[np] + ch * 8) * 4, bl);
                #pragma unroll
                for (int sub = 0; sub < 2; sub++) {
                    int nt = np * 2 + sub;
                    #pragma unroll
                    for (int mt = 0; mt < 2; mt++) {
                        mma16(acc[mt][nt], ah[mt][0], ah[mt][1], ah[mt][2], ah[mt][3], bh[2*sub], bh[2*sub+1]);
                        mma16(acc[mt][nt], ah[mt][0], ah[mt][1], ah[mt][2], ah[mt][3], bl[2*sub], bl[2*sub+1]);
                        mma16(acc[mt][nt], al[mt][0], al[mt][1], al[mt][2], al[mt][3], bh[2*sub], bh[2*sub+1]);
                    }
                }
            }
        }
        __syncthreads();
    }

    const float bs = bias[0];
    #pragma unroll
    for (int mt = 0; mt < 2; mt++) {
        int row0 = m0 + wm * 32 + mt * 16 + gid;
        #pragma unroll
        for (int nt = 0; nt < 8; nt++) {
            int col = n0 + wn * 64 + nt * 8 + 2 * tig;
            *(float2*)&out[(size_t)row0 * D_ + col]       = make_float2(acc[mt][nt][0] + bs, acc[mt][nt][1] + bs);
            *(float2*)&out[(size_t)(row0 + 8) * D_ + col] = make_float2(acc[mt][nt][2] + bs, acc[mt][nt][3] + bs);
        }
    }
}

// ---------------------------------------------------------------------------
extern "C" void kernel_launch(void* const* d_in, const int* in_sizes, int n_in,
                              void* d_out, int out_size)
{
    const float* x    = (const float*)d_in[0];
    const int*   mask = (const int*)  d_in[1];
    const float* Wq   = (const float*)d_in[2];
    const float* Wk   = (const float*)d_in[3];
    const float* Wv   = (const float*)d_in[4];
    const float* Wo   = (const float*)d_in[5];
    const float* bias = (const float*)d_in[6];
    float*       out  = (float*)d_out;

    static bool attr_set = false;
    if (!attr_set) {
        cudaFuncSetAttribute(qkv_mma,  cudaFuncAttributeMaxDynamicSharedMemorySize,
                             QKV_SMEM_WORDS  * (int)sizeof(uint32_t));
        cudaFuncSetAttribute(attn_mma, cudaFuncAttributeMaxDynamicSharedMemorySize,
                             ATTN_SMEM_WORDS * (int)sizeof(uint32_t));
        cudaFuncSetAttribute(out_mma,  cudaFuncAttributeMaxDynamicSharedMemorySize,
                             OUT_SMEM_WORDS  * (int)sizeof(uint32_t));
        attr_set = true;
    }

    prep_w<<<(WQKV_WORDS + WO_WORDS) / 256, 256>>>(Wq, Wk, Wv, Wo);
    prep_x<<<X_WORDS / 256, 256>>>(x);
    qkv_mma<<<dim3(4, 32, 12), 256, QKV_SMEM_WORDS * sizeof(uint32_t)>>>(bias);
    transpose_v<<<dim3(8, 256), 256>>>();
    attn_mma<<<dim3(4, 256), 256, ATTN_SMEM_WORDS * sizeof(uint32_t)>>>(mask);
    out_mma<<<dim3(128, 4), 256, OUT_SMEM_WORDS * sizeof(uint32_t)>>>(bias, out);
}